// round 1
// baseline (speedup 1.0000x reference)
#include <cuda_runtime.h>
#include <math.h>

#define NPIX 9409
#define CIN  512
#define CMIX 1024
#define C1N  256
#define C2N  512
#define FELEMS 88529281  /* 9409*9409 */

// -------- scratch (static device allocations; runtime alloc is forbidden) ----
__device__ float d_xmix[CMIX * NPIX];     // [1024, 9409] K-major input mix
__device__ float d_wtT [CMIX * C1N];      // w_theta^T  [1024, 256]
__device__ float d_wgT [CMIX * C2N];      // w_g^T      [1024, 512]
__device__ float d_woT [C2N * CIN];       // w_out^T    [512, 512]
__device__ float d_t   [C1N * NPIX];      // theta feats [256, 9409]
__device__ float d_g   [C2N * NPIX];      // g feats     [512, 9409]
__device__ float d_gt  [NPIX * C2N];      // g^T         [9409, 512]
__device__ float d_f   [FELEMS];          // f           [9409, 9409] (row-major, row=n)
__device__ float d_G   [FELEMS];          // softmax(f)^T: d_G[m*N+n] = G[n][m]
__device__ float d_y   [C2N * NPIX];      // y           [512, 9409]
__device__ float d_rmax[NPIX];
__device__ float d_rinv[NPIX];

// ---------------------------------------------------------------------------
// concat [x ; pos] along channels -> xmix [1024, 9409]
__global__ void concat_k(const float* __restrict__ x, const float* __restrict__ pos) {
    int i = blockIdx.x * blockDim.x + threadIdx.x;
    const int half = CIN * NPIX;
    if (i < half) { d_xmix[i] = x[i]; d_xmix[i + half] = pos[i]; }
}

// generic transpose: in [R, C] row-major -> out [C, R] row-major
__global__ void transpose_k(const float* __restrict__ in, float* __restrict__ out,
                            int R, int C) {
    __shared__ float tile[32][33];
    int c0 = blockIdx.x * 32, r0 = blockIdx.y * 32;
    int tx = threadIdx.x, ty = threadIdx.y;  // 32 x 8
    #pragma unroll
    for (int i = 0; i < 32; i += 8) {
        int r = r0 + ty + i, c = c0 + tx;
        if (r < R && c < C) tile[ty + i][tx] = in[(long long)r * C + c];
    }
    __syncthreads();
    #pragma unroll
    for (int i = 0; i < 32; i += 8) {
        int c = c0 + ty + i, r = r0 + tx;
        if (c < C && r < R) out[(long long)c * R + r] = tile[tx][ty + i];
    }
}

// ---------------------------------------------------------------------------
// TN-form SGEMM: C[m,n] = epi( alpha * sum_k A[k*M+m] * B[k*N+n] )
// A: [K, M] row-major,  B: [K, N] row-major,  C: [M, N] row-major
// EPI 0: v = alpha*acc
// EPI 1: v = acc + bias[m]
// EPI 2: v = relu((acc + bias[m]) * (gamma[m]*BN_INV) + beta[m])
#define BN_INV 0.9999950000374997f

template <int EPI>
__global__ __launch_bounds__(256)
void gemm_tn(const float* __restrict__ A, const float* __restrict__ B,
             float* __restrict__ C, int M, int N, int K,
             const float* __restrict__ bias, const float* __restrict__ gamma,
             const float* __restrict__ beta, float alpha) {
    __shared__ float As[8][128];
    __shared__ float Bs[8][128];
    const int tid = threadIdx.x;
    const int m0 = blockIdx.y * 128;
    const int n0 = blockIdx.x * 128;
    const int tx = tid & 15;        // 16 cols of threads
    const int ty = tid >> 4;        // 16 rows of threads

    float acc[8][8];
    #pragma unroll
    for (int i = 0; i < 8; ++i)
        #pragma unroll
        for (int j = 0; j < 8; ++j) acc[i][j] = 0.f;

    const int kt = (K + 7) >> 3;
    for (int t = 0; t < kt; ++t) {
        const int kbase = t * 8;
        #pragma unroll
        for (int i = 0; i < 4; ++i) {
            int idx = tid + i * 256;
            int k = idx >> 7, mm = idx & 127;
            int gk = kbase + k;
            int gm = m0 + mm;
            int gn = n0 + mm;
            As[k][mm] = (gk < K && gm < M) ? A[(long long)gk * M + gm] : 0.f;
            Bs[k][mm] = (gk < K && gn < N) ? B[(long long)gk * N + gn] : 0.f;
        }
        __syncthreads();
        #pragma unroll
        for (int k = 0; k < 8; ++k) {
            float a[8], b[8];
            #pragma unroll
            for (int i = 0; i < 8; ++i) a[i] = As[k][ty * 8 + i];
            #pragma unroll
            for (int j = 0; j < 8; ++j) b[j] = Bs[k][tx * 8 + j];
            #pragma unroll
            for (int i = 0; i < 8; ++i)
                #pragma unroll
                for (int j = 0; j < 8; ++j)
                    acc[i][j] = fmaf(a[i], b[j], acc[i][j]);
        }
        __syncthreads();
    }

    #pragma unroll
    for (int i = 0; i < 8; ++i) {
        int gm = m0 + ty * 8 + i;
        if (gm < M) {
            float bv = 0.f, sc = 1.f, bt = 0.f;
            if (EPI >= 1) bv = bias[gm];
            if (EPI == 2) { sc = gamma[gm] * BN_INV; bt = beta[gm]; }
            #pragma unroll
            for (int j = 0; j < 8; ++j) {
                int gn = n0 + tx * 8 + j;
                if (gn < N) {
                    float v = acc[i][j];
                    if (EPI == 0) v *= alpha;
                    else if (EPI == 1) v += bv;
                    else v = fmaxf(fmaf(v + bv, sc, bt), 0.f);
                    C[(long long)gm * N + gn] = v;
                }
            }
        }
    }
}

// ---------------------------------------------------------------------------
// per-row online (max, sumexp) of f; one block per row
__global__ __launch_bounds__(256) void row_stats_k(int N) {
    const int row = blockIdx.x;
    const float* p = d_f + (long long)row * N;
    float m = -1e30f, s = 0.f;
    for (int j = threadIdx.x; j < N; j += 256) {
        float v = p[j];
        if (v > m) { s = s * __expf(m - v) + 1.f; m = v; }
        else       { s += __expf(v - m); }
    }
    __shared__ float sm[256], ss[256];
    sm[threadIdx.x] = m; ss[threadIdx.x] = s;
    __syncthreads();
    for (int off = 128; off > 0; off >>= 1) {
        if (threadIdx.x < off) {
            float m1 = sm[threadIdx.x], s1 = ss[threadIdx.x];
            float m2 = sm[threadIdx.x + off], s2 = ss[threadIdx.x + off];
            float mm = fmaxf(m1, m2);
            sm[threadIdx.x] = mm;
            ss[threadIdx.x] = s1 * __expf(m1 - mm) + s2 * __expf(m2 - mm);
        }
        __syncthreads();
    }
    if (threadIdx.x == 0) { d_rmax[row] = sm[0]; d_rinv[row] = 1.f / ss[0]; }
}

// exp-normalize + transpose: d_G[m*N+n] = exp(f[n*N+m]-rmax[n])*rinv[n]
__global__ void softmax_transpose_k(int N) {
    __shared__ float tile[32][33];
    int m0 = blockIdx.x * 32, n0 = blockIdx.y * 32;
    int tx = threadIdx.x, ty = threadIdx.y;  // 32 x 8
    #pragma unroll
    for (int r = 0; r < 32; r += 8) {
        int n = n0 + ty + r, m = m0 + tx;
        if (n < N && m < N)
            tile[ty + r][tx] = __expf(d_f[(long long)n * N + m] - d_rmax[n]) * d_rinv[n];
    }
    __syncthreads();
    #pragma unroll
    for (int r = 0; r < 32; r += 8) {
        int m = m0 + ty + r, n = n0 + tx;
        if (m < N && n < N)
            d_G[(long long)m * N + n] = tile[tx][ty + r];
    }
}

// ---------------------------------------------------------------------------
extern "C" void kernel_launch(void* const* d_in, const int* in_sizes, int n_in,
                              void* d_out, int out_size) {
    const float* x       = (const float*)d_in[0];
    const float* pos     = (const float*)d_in[1];
    const float* w_theta = (const float*)d_in[2];
    const float* b_theta = (const float*)d_in[3];
    const float* gamma_t = (const float*)d_in[4];
    const float* beta_t  = (const float*)d_in[5];
    const float* w_g     = (const float*)d_in[6];
    const float* b_g     = (const float*)d_in[7];
    const float* w_out   = (const float*)d_in[8];
    const float* b_out   = (const float*)d_in[9];
    float* out = (float*)d_out;

    float *p_xmix, *p_wtT, *p_wgT, *p_woT, *p_t, *p_g, *p_gt, *p_f, *p_G, *p_y;
    cudaGetSymbolAddress((void**)&p_xmix, d_xmix);
    cudaGetSymbolAddress((void**)&p_wtT,  d_wtT);
    cudaGetSymbolAddress((void**)&p_wgT,  d_wgT);
    cudaGetSymbolAddress((void**)&p_woT,  d_woT);
    cudaGetSymbolAddress((void**)&p_t,    d_t);
    cudaGetSymbolAddress((void**)&p_g,    d_g);
    cudaGetSymbolAddress((void**)&p_gt,   d_gt);
    cudaGetSymbolAddress((void**)&p_f,    d_f);
    cudaGetSymbolAddress((void**)&p_G,    d_G);
    cudaGetSymbolAddress((void**)&p_y,    d_y);

    const int N = NPIX;
    dim3 tb(32, 8);

    // 1) xmix = [x ; pos]
    concat_k<<<(CIN * NPIX + 255) / 256, 256>>>(x, pos);

    // 2) transpose weights into K-major form
    transpose_k<<<dim3(CMIX / 32, C1N / 32), tb>>>(w_theta, p_wtT, C1N, CMIX);
    transpose_k<<<dim3(CMIX / 32, C2N / 32), tb>>>(w_g,     p_wgT, C2N, CMIX);
    transpose_k<<<dim3(C2N  / 32, CIN / 32), tb>>>(w_out,   p_woT, CIN, C2N);

    // 3) theta = relu(bn(W_t @ xmix + b))   [256, N]
    gemm_tn<2><<<dim3((N + 127) / 128, (C1N + 127) / 128), 256>>>(
        p_wtT, p_xmix, p_t, C1N, N, CMIX, b_theta, gamma_t, beta_t, 1.f);

    // 4) g = W_g @ xmix + b_g               [512, N]
    gemm_tn<1><<<dim3((N + 127) / 128, (C2N + 127) / 128), 256>>>(
        p_wgT, p_xmix, p_g, C2N, N, CMIX, b_g, nullptr, nullptr, 1.f);

    // 5) g^T [N, 512]
    transpose_k<<<dim3((N + 31) / 32, (C2N + 31) / 32), tb>>>(p_g, p_gt, C2N, N);

    // 6) f = t^T t / 16                     [N, N]
    gemm_tn<0><<<dim3((N + 127) / 128, (N + 127) / 128), 256>>>(
        p_t, p_t, p_f, N, N, C1N, nullptr, nullptr, nullptr, 0.0625f);

    // 7) softmax row stats + exp-normalize-transpose -> G^T
    row_stats_k<<<N, 256>>>(N);
    softmax_transpose_k<<<dim3((N + 31) / 32, (N + 31) / 32), tb>>>(N);

    // 8) y[c,n] = sum_m g[c,m] G[n,m]       [512, N]
    gemm_tn<0><<<dim3((N + 127) / 128, (C2N + 127) / 128), 256>>>(
        p_gt, p_G, p_y, C2N, N, N, nullptr, nullptr, nullptr, 1.f);

    // 9) out = W_out @ y + b_out            [512, N]
    gemm_tn<1><<<dim3((N + 127) / 128, (CIN + 127) / 128), 256>>>(
        p_woT, p_y, out, CIN, N, C2N, b_out, nullptr, nullptr, 1.f);
}

// round 3
// speedup vs baseline: 1.6185x; 1.6185x over previous
#include <cuda_runtime.h>
#include <cstdint>
#include <math.h>

#define NPIX 9409
#define LDF  9412          /* padded row stride for f/g */
#define CIN  512
#define CMIX 1024
#define C1N  256
#define C2N  512
#define BN_INV 0.9999950000374997f

// ------------------------- scratch (static device) --------------------------
__device__ float d_xmixT[NPIX * CMIX];        // [9409, 1024]
__device__ float d_tT  [NPIX * C1N];          // [9409, 256]
__device__ float d_g   [C2N * LDF];           // [512, 9412]
__device__ float d_f   [NPIX * LDF];          // [9409, 9412]  f -> exp(f-max) in place
__device__ float d_yT  [NPIX * C2N];          // [9409, 512]
__device__ float d_rinv[NPIX];

// ------------------------- helpers ------------------------------------------
__device__ __forceinline__ uint32_t f2tf(float v) {
    uint32_t u;
    asm("cvt.rna.tf32.f32 %0, %1;" : "=r"(u) : "f"(v));
    return u;
}

__device__ __forceinline__ void mma_tf32(float c[4], uint32_t a0, uint32_t a1,
                                         uint32_t a2, uint32_t a3,
                                         uint32_t b0, uint32_t b1) {
    asm volatile(
        "mma.sync.aligned.m16n8k8.row.col.f32.tf32.tf32.f32 "
        "{%0,%1,%2,%3}, {%4,%5,%6,%7}, {%8,%9}, {%0,%1,%2,%3};"
        : "+f"(c[0]), "+f"(c[1]), "+f"(c[2]), "+f"(c[3])
        : "r"(a0), "r"(a1), "r"(a2), "r"(a3), "r"(b0), "r"(b1));
}

// fast exp on the FMA pipe (no MUFU)
__device__ __forceinline__ float fexp(float x) {
    x = fmaxf(x, -87.0f);
    float t = x * 1.4426950408889634f;
    float fl = floorf(t);
    float f = t - fl;
    float p = 1.52527338e-5f;
    p = fmaf(p, f, 1.54035304e-4f);
    p = fmaf(p, f, 1.33335581e-3f);
    p = fmaf(p, f, 9.61812911e-3f);
    p = fmaf(p, f, 5.55041087e-2f);
    p = fmaf(p, f, 2.40226507e-1f);
    p = fmaf(p, f, 6.93147181e-1f);
    p = fmaf(p, f, 1.0f);
    int i = (int)fl;
    return p * __int_as_float((i + 127) << 23);
}

// ------------------------- concat + transpose -------------------------------
__global__ void concatT_k(const float* __restrict__ x, const float* __restrict__ pos) {
    __shared__ float tile[32][33];
    const float* S = blockIdx.z ? pos : x;
    int c0 = blockIdx.y * 32, n0 = blockIdx.x * 32;
    int tx = threadIdx.x, ty = threadIdx.y;
    #pragma unroll
    for (int i = 0; i < 32; i += 8) {
        int c = c0 + ty + i, n = n0 + tx;
        if (n < NPIX) tile[ty + i][tx] = S[(size_t)c * NPIX + n];
    }
    __syncthreads();
    int kbase = blockIdx.z * 512 + c0;
    #pragma unroll
    for (int i = 0; i < 32; i += 8) {
        int n = n0 + ty + i;
        if (n < NPIX) d_xmixT[(size_t)n * CMIX + kbase + tx] = tile[tx][ty + i];
    }
}

// ------------------------- mma.sync tf32 GEMM -------------------------------
// D[M,N] = epi( sum_k A[m,k]*B[n,k] );  A [M,K] lda, B [N,K] ldb, C [M,N] ldc
// EPI 0: *alpha   1: +p1[m]   2: relu((acc+p1[n])*p2[n]*BN_INV+p3[n])   3: *p1[m]
template <int EPI>
__global__ void __launch_bounds__(256)
gemm_mma(const float* __restrict__ A, const float* __restrict__ B, float* __restrict__ C,
         int M, int Nn, int K, int lda, int ldb, int ldc,
         const float* __restrict__ p1, const float* __restrict__ p2,
         const float* __restrict__ p3, float alpha) {
    __shared__ float As[128][36];
    __shared__ float Bs[128][36];

    const int tid  = threadIdx.x;
    const int lane = tid & 31, wid = tid >> 5;
    const int wm = wid & 1;          // 2 warp rows  (64 rows each)
    const int wn = wid >> 1;         // 4 warp cols  (32 cols each)
    const int g   = lane >> 2;       // 0..7
    const int tig = lane & 3;        // 0..3
    const int m0 = blockIdx.y * 128, n0 = blockIdx.x * 128;

    float acc[4][4][4];
    #pragma unroll
    for (int mt = 0; mt < 4; ++mt)
        #pragma unroll
        for (int nt = 0; nt < 4; ++nt)
            #pragma unroll
            for (int c = 0; c < 4; ++c) acc[mt][nt][c] = 0.f;

    const int lr = tid >> 3;           // 0..31
    const int kv = (tid & 7) << 2;     // 0,4,...,28
    const int KT = (K + 31) >> 5;

    for (int t = 0; t < KT; ++t) {
        const int kb = t << 5;
        const int gk = kb + kv;
        const bool kfull = (gk + 3) < K;
        #pragma unroll
        for (int i = 0; i < 4; ++i) {
            int row = lr + i * 32;
            float4 va = make_float4(0.f, 0.f, 0.f, 0.f);
            int gm = m0 + row;
            if (gm < M) {
                const float* pa = A + (size_t)gm * lda + gk;
                if (kfull) va = *(const float4*)pa;
                else {
                    if (gk     < K) va.x = pa[0];
                    if (gk + 1 < K) va.y = pa[1];
                    if (gk + 2 < K) va.z = pa[2];
                }
            }
            va.x = __uint_as_float(f2tf(va.x));
            va.y = __uint_as_float(f2tf(va.y));
            va.z = __uint_as_float(f2tf(va.z));
            va.w = __uint_as_float(f2tf(va.w));
            *(float4*)&As[row][kv] = va;

            float4 vb = make_float4(0.f, 0.f, 0.f, 0.f);
            int gn = n0 + row;
            if (gn < Nn) {
                const float* pb = B + (size_t)gn * ldb + gk;
                if (kfull) vb = *(const float4*)pb;
                else {
                    if (gk     < K) vb.x = pb[0];
                    if (gk + 1 < K) vb.y = pb[1];
                    if (gk + 2 < K) vb.z = pb[2];
                }
            }
            vb.x = __uint_as_float(f2tf(vb.x));
            vb.y = __uint_as_float(f2tf(vb.y));
            vb.z = __uint_as_float(f2tf(vb.z));
            vb.w = __uint_as_float(f2tf(vb.w));
            *(float4*)&Bs[row][kv] = vb;
        }
        __syncthreads();

        #pragma unroll
        for (int ks = 0; ks < 4; ++ks) {
            const int kk = ks * 8;
            uint32_t bf[4][2];
            #pragma unroll
            for (int nt = 0; nt < 4; ++nt) {
                int col = wn * 32 + nt * 8 + g;
                bf[nt][0] = __float_as_uint(Bs[col][kk + tig]);
                bf[nt][1] = __float_as_uint(Bs[col][kk + tig + 4]);
            }
            uint32_t af[4][4];
            #pragma unroll
            for (int mt = 0; mt < 4; ++mt) {
                int row = wm * 64 + mt * 16;
                af[mt][0] = __float_as_uint(As[row + g    ][kk + tig]);
                af[mt][1] = __float_as_uint(As[row + g + 8][kk + tig]);
                af[mt][2] = __float_as_uint(As[row + g    ][kk + tig + 4]);
                af[mt][3] = __float_as_uint(As[row + g + 8][kk + tig + 4]);
            }
            #pragma unroll
            for (int mt = 0; mt < 4; ++mt)
                #pragma unroll
                for (int nt = 0; nt < 4; ++nt)
                    mma_tf32(acc[mt][nt], af[mt][0], af[mt][1], af[mt][2], af[mt][3],
                             bf[nt][0], bf[nt][1]);
        }
        __syncthreads();
    }

    // ------------------------- epilogue -------------------------
    #pragma unroll
    for (int mt = 0; mt < 4; ++mt) {
        #pragma unroll
        for (int half = 0; half < 2; ++half) {
            int gm = m0 + wm * 64 + mt * 16 + g + half * 8;
            if (gm >= M) continue;
            float rp = 0.f;
            if (EPI == 1 || EPI == 3) rp = p1[gm];
            float* crow = C + (size_t)gm * ldc;
            #pragma unroll
            for (int nt = 0; nt < 4; ++nt) {
                #pragma unroll
                for (int cc = 0; cc < 2; ++cc) {
                    int gn = n0 + wn * 32 + nt * 8 + tig * 2 + cc;
                    if (gn < Nn) {
                        float v = acc[mt][nt][half * 2 + cc];
                        if (EPI == 0)      v *= alpha;
                        else if (EPI == 1) v += rp;
                        else if (EPI == 2) v = fmaxf(fmaf(v + p1[gn], p2[gn] * BN_INV, p3[gn]), 0.f);
                        else               v *= rp;
                        crow[gn] = v;
                    }
                }
            }
        }
    }
}

// ------------------------- softmax: max + exp in place + 1/sum --------------
__global__ void __launch_bounds__(256) softmax_k() {
    __shared__ float buf[NPIX];
    __shared__ float red[256];
    const int row = blockIdx.x;
    float* p = d_f + (size_t)row * LDF;
    float m = -1e30f;
    for (int j = threadIdx.x; j < NPIX; j += 256) {
        float v = p[j];
        buf[j] = v;
        m = fmaxf(m, v);
    }
    red[threadIdx.x] = m;
    __syncthreads();
    for (int off = 128; off > 0; off >>= 1) {
        if (threadIdx.x < off) red[threadIdx.x] = fmaxf(red[threadIdx.x], red[threadIdx.x + off]);
        __syncthreads();
    }
    const float rm = red[0];
    __syncthreads();
    float s = 0.f;
    for (int j = threadIdx.x; j < NPIX; j += 256) {
        float e = fexp(buf[j] - rm);
        p[j] = e;
        s += e;
    }
    red[threadIdx.x] = s;
    __syncthreads();
    for (int off = 128; off > 0; off >>= 1) {
        if (threadIdx.x < off) red[threadIdx.x] += red[threadIdx.x + off];
        __syncthreads();
    }
    if (threadIdx.x == 0) d_rinv[row] = 1.f / red[0];
}

// ---------------------------------------------------------------------------
extern "C" void kernel_launch(void* const* d_in, const int* in_sizes, int n_in,
                              void* d_out, int out_size) {
    const float* x       = (const float*)d_in[0];
    const float* pos     = (const float*)d_in[1];
    const float* w_theta = (const float*)d_in[2];
    const float* b_theta = (const float*)d_in[3];
    const float* gamma_t = (const float*)d_in[4];
    const float* beta_t  = (const float*)d_in[5];
    const float* w_g     = (const float*)d_in[6];
    const float* b_g     = (const float*)d_in[7];
    const float* w_out   = (const float*)d_in[8];
    const float* b_out   = (const float*)d_in[9];
    float* out = (float*)d_out;

    float *p_xmixT, *p_tT, *p_g, *p_f, *p_yT, *p_rinv;
    cudaGetSymbolAddress((void**)&p_xmixT, d_xmixT);
    cudaGetSymbolAddress((void**)&p_tT,    d_tT);
    cudaGetSymbolAddress((void**)&p_g,     d_g);
    cudaGetSymbolAddress((void**)&p_f,     d_f);
    cudaGetSymbolAddress((void**)&p_yT,    d_yT);
    cudaGetSymbolAddress((void**)&p_rinv,  d_rinv);

    const int TM = 74;  // ceil(9409/128)

    // 1) xmixT = concat(x,pos)^T   [9409, 1024]
    concatT_k<<<dim3(295, 16, 2), dim3(32, 8)>>>(x, pos);

    // 2) tT = relu(bn(xmixT @ w_theta^T))   [9409, 256]
    gemm_mma<2><<<dim3(2, TM), 256>>>(
        p_xmixT, w_theta, p_tT, NPIX, C1N, CMIX, CMIX, CMIX, C1N,
        b_theta, gamma_t, beta_t, 1.f);

    // 3) g = w_g @ xmixT^T + b_g   [512, LDF-strided]
    gemm_mma<1><<<dim3(TM, 4), 256>>>(
        w_g, p_xmixT, p_g, C2N, NPIX, CMIX, CMIX, CMIX, LDF,
        b_g, nullptr, nullptr, 1.f);

    // 4) f = (tT @ tT^T) / 16      [9409, LDF-strided]
    gemm_mma<0><<<dim3(TM, TM), 256>>>(
        p_tT, p_tT, p_f, NPIX, NPIX, C1N, C1N, C1N, LDF,
        nullptr, nullptr, nullptr, 0.0625f);

    // 5) softmax rows: f := exp(f-max) in place, rinv = 1/rowsum
    softmax_k<<<NPIX, 256>>>();

    // 6) yT[n,c] = rinv[n] * sum_m E[n,m] g[c,m]    [9409, 512]
    gemm_mma<3><<<dim3(4, TM), 256>>>(
        p_f, p_g, p_yT, NPIX, C2N, NPIX, LDF, LDF, C2N,
        p_rinv, nullptr, nullptr, 1.f);

    // 7) out = w_out @ yT^T + b_out   [512, 9409]
    gemm_mma<1><<<dim3(TM, 4), 256>>>(
        w_out, p_yT, out, CIN, NPIX, C2N, C2N, C2N, NPIX,
        b_out, nullptr, nullptr, 1.f);
}

// round 4
// speedup vs baseline: 5.4755x; 3.3831x over previous
#include <cuda_runtime.h>
#include <cstdint>
#include <math.h>

#define NPIX 9409
#define LDF  9412          /* padded row stride for f/g; pads stay 0 forever */
#define CIN  512
#define CMIX 1024
#define C1N  256
#define C2N  512
#define BN_INV 0.9999950000374997f

// ------------------------- scratch (static device) --------------------------
__device__ float d_xmixT[NPIX * CMIX];        // [9409, 1024] (tf32-rounded)
__device__ float d_tT  [NPIX * C1N];          // [9409, 256]  (tf32-rounded)
__device__ float d_g   [C2N * LDF];           // [512, 9412]  (tf32-rounded)
__device__ float d_f   [NPIX * LDF];          // [9409, 9412] f -> exp (tf32-rounded)
__device__ float d_yT  [NPIX * C2N];          // [9409, 512]  (tf32-rounded)
__device__ float d_rinv[NPIX];
__device__ float d_wtR [C1N * CMIX];          // rounded weights
__device__ float d_wgR [C2N * CMIX];
__device__ float d_woR [CIN * C2N];

// ------------------------- helpers ------------------------------------------
__device__ __forceinline__ uint32_t f2tf(float v) {
    uint32_t u;
    asm("cvt.rna.tf32.f32 %0, %1;" : "=r"(u) : "f"(v));
    return u;
}
__device__ __forceinline__ float rtf(float v) { return __uint_as_float(f2tf(v)); }

__device__ __forceinline__ void mma_tf32(float c[4], uint32_t a0, uint32_t a1,
                                         uint32_t a2, uint32_t a3,
                                         uint32_t b0, uint32_t b1) {
    asm volatile(
        "mma.sync.aligned.m16n8k8.row.col.f32.tf32.tf32.f32 "
        "{%0,%1,%2,%3}, {%4,%5,%6,%7}, {%8,%9}, {%0,%1,%2,%3};"
        : "+f"(c[0]), "+f"(c[1]), "+f"(c[2]), "+f"(c[3])
        : "r"(a0), "r"(a1), "r"(a2), "r"(a3), "r"(b0), "r"(b1));
}

// fast exp on the FMA pipe (no MUFU)
__device__ __forceinline__ float fexp(float x) {
    x = fmaxf(x, -87.0f);
    float t = x * 1.4426950408889634f;
    float fl = floorf(t);
    float f = t - fl;
    float p = 1.52527338e-5f;
    p = fmaf(p, f, 1.54035304e-4f);
    p = fmaf(p, f, 1.33335581e-3f);
    p = fmaf(p, f, 9.61812911e-3f);
    p = fmaf(p, f, 5.55041087e-2f);
    p = fmaf(p, f, 2.40226507e-1f);
    p = fmaf(p, f, 6.93147181e-1f);
    p = fmaf(p, f, 1.0f);
    int i = (int)fl;
    return p * __int_as_float((i + 127) << 23);
}

// ------------------------- small prep kernels -------------------------------
__global__ void round_k(const float* __restrict__ in, float* __restrict__ out, int n) {
    int i = blockIdx.x * 256 + threadIdx.x;
    if (i < n) out[i] = rtf(in[i]);
}

// xmixT[n, k] = tf32round( (k<512) ? x[k, n] : pos[k-512, n] )
__global__ void concatT_k(const float* __restrict__ x, const float* __restrict__ pos) {
    __shared__ float tile[32][33];
    const float* S = blockIdx.z ? pos : x;
    int c0 = blockIdx.y * 32, n0 = blockIdx.x * 32;
    int tx = threadIdx.x, ty = threadIdx.y;
    #pragma unroll
    for (int i = 0; i < 32; i += 8) {
        int c = c0 + ty + i, n = n0 + tx;
        if (n < NPIX) tile[ty + i][tx] = S[(size_t)c * NPIX + n];
    }
    __syncthreads();
    int kbase = blockIdx.z * 512 + c0;
    #pragma unroll
    for (int i = 0; i < 32; i += 8) {
        int n = n0 + ty + i;
        if (n < NPIX) d_xmixT[(size_t)n * CMIX + kbase + tx] = rtf(tile[tx][ty + i]);
    }
}

// ------------------------- mma.sync tf32 GEMM, cp.async pipelined -----------
// D[M,N] = epi( sum_k A[m,k]*B[n,k] );  A [M,K] lda, B [N,K] ldb, C [M,N] ldc
// EPI 0: *alpha   1: +p1[n-idx? no: m]   2: relu((acc+p1[gn])*p2[gn]*BN_INV+p3[gn])   3: *p1[gm]
// ROUND: round output to tf32
#define GEMM_SMEM 73728   /* 2 buffers x (A 18432 + B 18432) */

template <int EPI, int ROUND>
__global__ void __launch_bounds__(256, 2)
gemm_mma(const float* __restrict__ A, const float* __restrict__ B, float* __restrict__ C,
         int M, int Nn, int K, int lda, int ldb, int ldc,
         const float* __restrict__ p1, const float* __restrict__ p2,
         const float* __restrict__ p3, float alpha) {
    extern __shared__ char dsm[];
    float* smf = (float*)dsm;
    const uint32_t sbase = (uint32_t)__cvta_generic_to_shared(dsm);

    const int tid  = threadIdx.x;
    const int lane = tid & 31, wid = tid >> 5;
    const int wm = wid & 1;          // 2 warp rows (64 m each)
    const int wn = wid >> 1;         // 4 warp cols (32 n each)
    const int g   = lane >> 2;       // 0..7
    const int tig = lane & 3;        // 0..3
    const int m0 = blockIdx.y * 128, n0 = blockIdx.x * 128;

    const int lr  = tid >> 3;        // 0..31
    const int kv4 = (tid & 7) << 2;  // 0,4,...,28

    float acc[4][4][4];
    #pragma unroll
    for (int mt = 0; mt < 4; ++mt)
        #pragma unroll
        for (int nt = 0; nt < 4; ++nt)
            #pragma unroll
            for (int c = 0; c < 4; ++c) acc[mt][nt][c] = 0.f;

    const int KT = (K + 31) >> 5;

    auto issue = [&](int t) {
        const int bsel = t & 1;
        const int gk = (t << 5) + kv4;
        uint32_t sa = sbase + (uint32_t)bsel * 36864u;
        uint32_t sb = sa + 18432u;
        #pragma unroll
        for (int i = 0; i < 4; ++i) {
            int row = lr + (i << 5);
            uint32_t off = (uint32_t)(row * 144 + (kv4 << 2));
            const float* pa = A + (size_t)(m0 + row) * lda + gk;
            int sza = ((m0 + row) < M && gk < K) ? 16 : 0;
            if (!sza) pa = A;
            asm volatile("cp.async.cg.shared.global [%0], [%1], 16, %2;"
                         :: "r"(sa + off), "l"(pa), "r"(sza) : "memory");
            const float* pb = B + (size_t)(n0 + row) * ldb + gk;
            int szb = ((n0 + row) < Nn && gk < K) ? 16 : 0;
            if (!szb) pb = B;
            asm volatile("cp.async.cg.shared.global [%0], [%1], 16, %2;"
                         :: "r"(sb + off), "l"(pb), "r"(szb) : "memory");
        }
        asm volatile("cp.async.commit_group;" ::: "memory");
    };

    issue(0);
    for (int t = 0; t < KT; ++t) {
        if (t + 1 < KT) {
            issue(t + 1);
            asm volatile("cp.async.wait_group 1;" ::: "memory");
        } else {
            asm volatile("cp.async.wait_group 0;" ::: "memory");
        }
        __syncthreads();

        const float* As = smf + (t & 1) * 9216;
        const float* Bs = As + 4608;

        #pragma unroll
        for (int ks = 0; ks < 4; ++ks) {
            const int kk = ks * 8;
            uint32_t bf[4][2];
            #pragma unroll
            for (int nt = 0; nt < 4; ++nt) {
                int col = wn * 32 + nt * 8 + g;
                bf[nt][0] = __float_as_uint(Bs[col * 36 + kk + tig]);
                bf[nt][1] = __float_as_uint(Bs[col * 36 + kk + tig + 4]);
            }
            #pragma unroll
            for (int mt = 0; mt < 4; ++mt) {
                int row = wm * 64 + mt * 16;
                uint32_t a0 = __float_as_uint(As[(row + g    ) * 36 + kk + tig]);
                uint32_t a1 = __float_as_uint(As[(row + g + 8) * 36 + kk + tig]);
                uint32_t a2 = __float_as_uint(As[(row + g    ) * 36 + kk + tig + 4]);
                uint32_t a3 = __float_as_uint(As[(row + g + 8) * 36 + kk + tig + 4]);
                #pragma unroll
                for (int nt = 0; nt < 4; ++nt)
                    mma_tf32(acc[mt][nt], a0, a1, a2, a3, bf[nt][0], bf[nt][1]);
            }
        }
        __syncthreads();
    }

    // ------------------------- epilogue -------------------------
    #pragma unroll
    for (int mt = 0; mt < 4; ++mt) {
        #pragma unroll
        for (int half = 0; half < 2; ++half) {
            int gm = m0 + wm * 64 + mt * 16 + g + half * 8;
            if (gm >= M) continue;
            float rp = 0.f;
            if (EPI == 1 || EPI == 3) rp = p1[gm];
            float* crow = C + (size_t)gm * ldc;
            #pragma unroll
            for (int nt = 0; nt < 4; ++nt) {
                #pragma unroll
                for (int cc = 0; cc < 2; ++cc) {
                    int gn = n0 + wn * 32 + nt * 8 + tig * 2 + cc;
                    if (gn < Nn) {
                        float v = acc[mt][nt][half * 2 + cc];
                        if (EPI == 0)      v *= alpha;
                        else if (EPI == 1) v += rp;
                        else if (EPI == 2) v = fmaxf(fmaf(v + p1[gn], p2[gn] * BN_INV, p3[gn]), 0.f);
                        else               v *= rp;
                        if (ROUND) v = rtf(v);
                        crow[gn] = v;
                    }
                }
            }
        }
    }
}

// ------------------------- softmax: max + exp in place + 1/sum --------------
__global__ void __launch_bounds__(256) softmax_k() {
    __shared__ float buf[NPIX];
    __shared__ float red[256];
    const int row = blockIdx.x;
    float* p = d_f + (size_t)row * LDF;
    float m = -1e30f;
    for (int j = threadIdx.x; j < NPIX; j += 256) {
        float v = p[j];
        buf[j] = v;
        m = fmaxf(m, v);
    }
    red[threadIdx.x] = m;
    __syncthreads();
    for (int off = 128; off > 0; off >>= 1) {
        if (threadIdx.x < off) red[threadIdx.x] = fmaxf(red[threadIdx.x], red[threadIdx.x + off]);
        __syncthreads();
    }
    const float rm = red[0];
    __syncthreads();
    float s = 0.f;
    for (int j = threadIdx.x; j < NPIX; j += 256) {
        float e = rtf(fexp(buf[j] - rm));   // store tf32-rounded; sum the same values
        p[j] = e;
        s += e;
    }
    red[threadIdx.x] = s;
    __syncthreads();
    for (int off = 128; off > 0; off >>= 1) {
        if (threadIdx.x < off) red[threadIdx.x] += red[threadIdx.x + off];
        __syncthreads();
    }
    if (threadIdx.x == 0) d_rinv[row] = 1.f / red[0];
}

// ---------------------------------------------------------------------------
extern "C" void kernel_launch(void* const* d_in, const int* in_sizes, int n_in,
                              void* d_out, int out_size) {
    const float* x       = (const float*)d_in[0];
    const float* pos     = (const float*)d_in[1];
    const float* w_theta = (const float*)d_in[2];
    const float* b_theta = (const float*)d_in[3];
    const float* gamma_t = (const float*)d_in[4];
    const float* beta_t  = (const float*)d_in[5];
    const float* w_g     = (const float*)d_in[6];
    const float* b_g     = (const float*)d_in[7];
    const float* w_out   = (const float*)d_in[8];
    const float* b_out   = (const float*)d_in[9];
    float* out = (float*)d_out;

    cudaFuncSetAttribute(gemm_mma<2,1>, cudaFuncAttributeMaxDynamicSharedMemorySize, GEMM_SMEM);
    cudaFuncSetAttribute(gemm_mma<1,1>, cudaFuncAttributeMaxDynamicSharedMemorySize, GEMM_SMEM);
    cudaFuncSetAttribute(gemm_mma<0,0>, cudaFuncAttributeMaxDynamicSharedMemorySize, GEMM_SMEM);
    cudaFuncSetAttribute(gemm_mma<3,1>, cudaFuncAttributeMaxDynamicSharedMemorySize, GEMM_SMEM);
    cudaFuncSetAttribute(gemm_mma<1,0>, cudaFuncAttributeMaxDynamicSharedMemorySize, GEMM_SMEM);

    float *p_xmixT, *p_tT, *p_g, *p_f, *p_yT, *p_rinv, *p_wtR, *p_wgR, *p_woR;
    cudaGetSymbolAddress((void**)&p_xmixT, d_xmixT);
    cudaGetSymbolAddress((void**)&p_tT,    d_tT);
    cudaGetSymbolAddress((void**)&p_g,     d_g);
    cudaGetSymbolAddress((void**)&p_f,     d_f);
    cudaGetSymbolAddress((void**)&p_yT,    d_yT);
    cudaGetSymbolAddress((void**)&p_rinv,  d_rinv);
    cudaGetSymbolAddress((void**)&p_wtR,   d_wtR);
    cudaGetSymbolAddress((void**)&p_wgR,   d_wgR);
    cudaGetSymbolAddress((void**)&p_woR,   d_woR);

    const int TM = 74;  // ceil(9409/128)

    // 0) round weights to tf32 once per launch
    round_k<<<(C1N * CMIX + 255) / 256, 256>>>(w_theta, p_wtR, C1N * CMIX);
    round_k<<<(C2N * CMIX + 255) / 256, 256>>>(w_g,     p_wgR, C2N * CMIX);
    round_k<<<(CIN * C2N  + 255) / 256, 256>>>(w_out,   p_woR, CIN * C2N);

    // 1) xmixT = round(concat(x,pos)^T)   [9409, 1024]
    concatT_k<<<dim3(295, 16, 2), dim3(32, 8)>>>(x, pos);

    // 2) tT = round(relu(bn(xmixT @ w_theta^T)))   [9409, 256]
    gemm_mma<2,1><<<dim3(2, TM), 256, GEMM_SMEM>>>(
        p_xmixT, p_wtR, p_tT, NPIX, C1N, CMIX, CMIX, CMIX, C1N,
        b_theta, gamma_t, beta_t, 1.f);

    // 3) g = round(w_g @ xmixT^T + b_g)   [512, LDF]
    gemm_mma<1,1><<<dim3(TM, 4), 256, GEMM_SMEM>>>(
        p_wgR, p_xmixT, p_g, C2N, NPIX, CMIX, CMIX, CMIX, LDF,
        b_g, nullptr, nullptr, 1.f);

    // 4) f = (tT @ tT^T) / 16             [9409, LDF]
    gemm_mma<0,0><<<dim3(TM, TM), 256, GEMM_SMEM>>>(
        p_tT, p_tT, p_f, NPIX, NPIX, C1N, C1N, C1N, LDF,
        nullptr, nullptr, nullptr, 0.0625f);

    // 5) softmax rows: f := round(exp(f-max)), rinv = 1/rowsum
    softmax_k<<<NPIX, 256>>>();

    // 6) yT[n,c] = round(rinv[n] * sum_m E[n,m] g[c,m])   [9409, 512]
    //    K = LDF: pad columns of f and g are zero, contribute nothing
    gemm_mma<3,1><<<dim3(4, TM), 256, GEMM_SMEM>>>(
        p_f, p_g, p_yT, NPIX, C2N, LDF, LDF, LDF, C2N,
        p_rinv, nullptr, nullptr, 1.f);

    // 7) out = w_out @ yT^T + b_out       [512, 9409]
    gemm_mma<1,0><<<dim3(TM, 4), 256, GEMM_SMEM>>>(
        p_woR, p_yT, out, CIN, NPIX, C2N, C2N, C2N, NPIX,
        b_out, nullptr, nullptr, 1.f);
}